// round 1
// baseline (speedup 1.0000x reference)
#include <cuda_runtime.h>

// Problem constants (shapes fixed by the dataset)
#define NB   16          // batch
#define C    256         // channels
#define HH   128
#define WW   128
#define HW   (HH*WW)     // 16384 pixels per image
#define CLS  9
#define P    (NB*HW)     // 262144 total pixels
#define NT   256         // threads per block

// Scratch (no allocations allowed)
__device__ float         g_sums[C*CLS];
__device__ int           g_counts[CLS];
__device__ unsigned char g_labels[P];

// ---------------------------------------------------------------------------
// 0) zero the accumulators (graph replays must be deterministic)
// ---------------------------------------------------------------------------
__global__ void zero_kernel() {
    int i = blockIdx.x * blockDim.x + threadIdx.x;
    if (i < C*CLS) g_sums[i] = 0.0f;
    if (i < CLS)   g_counts[i] = 0;
}

// ---------------------------------------------------------------------------
// 1) per-pixel argmax over CLS logit planes -> labels[P] (uint8) + counts
//    float4-vectorized: each thread handles 4 consecutive pixels.
// ---------------------------------------------------------------------------
__global__ void __launch_bounds__(NT) argmax_kernel(const float* __restrict__ logit) {
    __shared__ int s_cnt[CLS];
    const int tid = threadIdx.x;
    if (tid < CLS) s_cnt[tid] = 0;
    __syncthreads();

    const int g   = blockIdx.x * NT + tid;   // float4-group index, 0..P/4-1
    const int n   = g >> 12;                 // g / (HW/4)
    const int hw4 = g & 4095;                // g % (HW/4)

    const float4* lp = (const float4*)logit;
    float4 best = lp[(size_t)(n*CLS + 0) * (HW/4) + hw4];
    uchar4 lab  = make_uchar4(0,0,0,0);
    #pragma unroll
    for (int cls = 1; cls < CLS; cls++) {
        float4 v = lp[(size_t)(n*CLS + cls) * (HW/4) + hw4];
        if (v.x > best.x) { best.x = v.x; lab.x = (unsigned char)cls; }
        if (v.y > best.y) { best.y = v.y; lab.y = (unsigned char)cls; }
        if (v.z > best.z) { best.z = v.z; lab.z = (unsigned char)cls; }
        if (v.w > best.w) { best.w = v.w; lab.w = (unsigned char)cls; }
    }
    ((uchar4*)g_labels)[g] = lab;

    atomicAdd(&s_cnt[lab.x], 1);
    atomicAdd(&s_cnt[lab.y], 1);
    atomicAdd(&s_cnt[lab.z], 1);
    atomicAdd(&s_cnt[lab.w], 1);
    __syncthreads();
    if (tid < CLS && s_cnt[tid] > 0) atomicAdd(&g_counts[tid], s_cnt[tid]);
}

// ---------------------------------------------------------------------------
// 2) accumulate: one block per (n,c) plane. Streams the plane (float4) with
//    the matching labels (uchar4, L2-resident) and scatters into per-thread
//    SMEM columns acc[cls][tid] (bank-conflict-free), then tree-reduces and
//    does 9 float atomics into g_sums[c][cls].
// ---------------------------------------------------------------------------
__global__ void __launch_bounds__(NT) accum_kernel(const float* __restrict__ feat) {
    __shared__ float acc[CLS * NT];
    const int tid = threadIdx.x;
    #pragma unroll
    for (int l = 0; l < CLS; l++) acc[l*NT + tid] = 0.0f;
    __syncthreads();

    const int nc = blockIdx.x;        // 0..NB*C-1
    const int n  = nc >> 8;           // nc / C
    const int c  = nc & 255;          // nc % C

    const float4* fp = (const float4*)feat + (size_t)nc * (HW/4);
    const uchar4* lp = (const uchar4*)g_labels + (size_t)n * (HW/4);

    #pragma unroll
    for (int k = 0; k < (HW/4)/NT; k++) {   // 16 iterations
        const int i = tid + k*NT;
        float4 v = fp[i];
        uchar4 l = lp[i];
        acc[l.x*NT + tid] += v.x;
        acc[l.y*NT + tid] += v.y;
        acc[l.z*NT + tid] += v.z;
        acc[l.w*NT + tid] += v.w;
    }
    __syncthreads();

    // tree reduce over tid for all 9 classes
    for (int s = NT/2; s > 0; s >>= 1) {
        if (tid < s) {
            #pragma unroll
            for (int l = 0; l < CLS; l++)
                acc[l*NT + tid] += acc[l*NT + tid + s];
        }
        __syncthreads();
    }

    if (tid < CLS) atomicAdd(&g_sums[c*CLS + tid], acc[tid*NT]);
}

// ---------------------------------------------------------------------------
// 3) emit: out[n][c][cls] = sums[c][cls] / max(count[cls], 1)
// ---------------------------------------------------------------------------
__global__ void out_kernel(float* __restrict__ out) {
    int i = blockIdx.x * blockDim.x + threadIdx.x;
    if (i >= NB*C*CLS) return;
    int rem = i % (C*CLS);
    int c   = rem / CLS;
    int cls = rem % CLS;
    float cnt = (float)g_counts[cls];
    out[i] = g_sums[c*CLS + cls] / fmaxf(cnt, 1.0f);
}

// ---------------------------------------------------------------------------
extern "C" void kernel_launch(void* const* d_in, const int* in_sizes, int n_in,
                              void* d_out, int out_size) {
    const float* feat  = (const float*)d_in[0];
    const float* logit = (const float*)d_in[1];
    float* out = (float*)d_out;

    zero_kernel<<<(C*CLS + NT - 1)/NT, NT>>>();
    argmax_kernel<<<(P/4)/NT, NT>>>(logit);          // 256 blocks
    accum_kernel<<<NB*C, NT>>>(feat);                // 4096 blocks
    out_kernel<<<(NB*C*CLS + NT - 1)/NT, NT>>>(out); // 144 blocks
}